// round 14
// baseline (speedup 1.0000x reference)
#include <cuda_runtime.h>
#include <cuda_bf16.h>

#define NNODES 512
#define NIN    256
#define NOUT   256
#define NT     32      // 512/16 node tiles
#define TS     16      // writer tile size

// Split-K partial buffers: A = A0 + A1 (bias folded into A0), B = B0 + B1.
__device__ float g_A0[NNODES * NOUT];
__device__ float g_A1[NNODES * NOUT];
__device__ float g_B0[NNODES * NOUT];
__device__ float g_B1[NNODES * NOUT];

// Producer-barrier counters (kernel 1 only; reset in-kernel each replay).
__device__ int g_cnt;    // GEMM-done arrivals
__device__ int g_pass;   // spin-passed arrivals (for safe reset)

__device__ __forceinline__ int ld_acquire(const int* p) {
    int v;
    asm volatile("ld.acquire.gpu.global.s32 %0, [%1];" : "=r"(v) : "l"(p) : "memory");
    return v;
}
__device__ __forceinline__ void red_release_add(int* p, int v) {
    asm volatile("red.release.gpu.global.add.s32 [%0], %1;" :: "l"(p), "r"(v) : "memory");
}

// ---------------------------------------------------------------------------
// Writer tile body (exact R12 logic, linearized tile id t in [0, 1024)).
//   t -> (bi = t>>5, bj = t&31); lower-triangle remapped to strict-upper twin
//   (mirror). A rows in registers, B tile in smem. __stcs streaming stores.
// Leading __syncthreads protects sB reuse between consecutive calls.
// ---------------------------------------------------------------------------
__device__ __forceinline__ void write_tile(int t, float* __restrict__ out,
                                           float* sB, int tid)
{
    __syncthreads();

    int bi = t >> 5;
    int bj = t & 31;
    bool mirror = false;
    if (bi > bj) {
        bi = (NT - 1) - bi;
        bj = (NT - 1) - bj;
        mirror = true;
    }
    const bool diag = (bi == bj);
    const int i0 = bi * TS;
    const int j0 = bj * TS;

    const int c  = (tid & 63) * 4;   // channel offset (float4 lane)
    const int ip = tid >> 6;         // ii sub-index 0..3

    // ---- A rows into registers (coalesced float4) ----
    float4 aR[4];
    #pragma unroll
    for (int ob = 0; ob < 4; ob++) {
        int r = i0 + ob * 4 + ip;
        float4 a0 = *reinterpret_cast<const float4*>(&g_A0[r * NOUT + c]);
        float4 a1 = *reinterpret_cast<const float4*>(&g_A1[r * NOUT + c]);
        aR[ob] = make_float4(a0.x + a1.x, a0.y + a1.y, a0.z + a1.z, a0.w + a1.w);
    }

    // ---- B tile (B0+B1) into smem, float4 coalesced ----
    #pragma unroll
    for (int s = 0; s < 4; s++) {
        int idx = tid + s * 256;      // float4 slot 0..1023
        int r   = idx >> 6;           // row 0..15
        int cc  = (idx & 63) * 4;
        float4 b0 = *reinterpret_cast<const float4*>(&g_B0[(j0 + r) * NOUT + cc]);
        float4 b1 = *reinterpret_cast<const float4*>(&g_B1[(j0 + r) * NOUT + cc]);
        *reinterpret_cast<float4*>(&sB[r * NOUT + cc]) =
            make_float4(b0.x + b1.x, b0.y + b1.y, b0.z + b1.z, b0.w + b1.w);
    }
    __syncthreads();

    if (!diag) {
        const size_t stride = mirror ? (size_t)NNODES * NOUT : (size_t)NOUT;
        #pragma unroll
        for (int ob = 0; ob < 4; ob++) {
            const int ii = ob * 4 + ip;
            const int i  = i0 + ii;
            const float4 a = aR[ob];
            float* p = mirror
                ? &out[((size_t)j0 * NNODES + i) * NOUT + c]
                : &out[((size_t)i * NNODES + j0) * NOUT + c];
            #pragma unroll 4
            for (int jj = 0; jj < TS; jj++) {
                float4 bb = *reinterpret_cast<const float4*>(&sB[jj * NOUT + c]);
                float4 v  = make_float4(a.x + bb.x, a.y + bb.y,
                                        a.z + bb.z, a.w + bb.w);
                __stcs(reinterpret_cast<float4*>(p), v);
                p += stride;
            }
        }
    } else {
        #pragma unroll
        for (int ob = 0; ob < 4; ob++) {
            const int ii = ob * 4 + ip;
            const int i  = i0 + ii;
            const float4 a = aR[ob];
            float* pij = &out[((size_t)i * NNODES + (j0 + ii + 1)) * NOUT + c];
            float* pji = &out[((size_t)(j0 + ii + 1) * NNODES + i) * NOUT + c];
            for (int jj = ii + 1; jj < TS; jj++) {
                float4 bb = *reinterpret_cast<const float4*>(&sB[jj * NOUT + c]);
                float4 v  = make_float4(a.x + bb.x, a.y + bb.y,
                                        a.z + bb.z, a.w + bb.w);
                __stcs(reinterpret_cast<float4*>(pij), v);
                __stcs(reinterpret_cast<float4*>(pji), v);
                pij += NOUT;
                pji += (size_t)NNODES * NOUT;
            }
            __stcs(reinterpret_cast<float4*>(
                &out[((size_t)i * NNODES + i) * NOUT + c]),
                make_float4(0.f, 0.f, 0.f, 0.f));
        }
    }
}

// ---------------------------------------------------------------------------
// Kernel 1: GEMM (128 blocks, 64x64x32 tiles, 4x4 micro-tile, double-buffered)
// then producer barrier, then each block writes 2 output tiles (tiles 0..255)
// while kernel 2 spins up under PDL.
// ---------------------------------------------------------------------------
__global__ void __launch_bounds__(256)
gemm_writer_kernel(const float* __restrict__ x,
                   const float* __restrict__ W,
                   const float* __restrict__ b,
                   float* __restrict__ out)
{
    __shared__ __align__(16) float xs[32 * 68];
    __shared__ __align__(16) float ws[32 * 68];
    __shared__ __align__(16) float sB[TS * NOUT];

    const int tid = threadIdx.x;
    const int bid = blockIdx.x;              // 0..127
    const int z   = bid >> 5;                // 0..3
    const int by  = (bid >> 2) & 7;          // i tile
    const int bx  = bid & 3;                 // o tile

    const int half = z >> 1;                 // 0: A, 1: B
    const int ks   = z & 1;                  // K-split index
    const int i0   = by * 64;
    const int o0   = bx * 64;
    const int kbase = ks * 128;
    const int woff  = half * NIN;

    const int tx  = tid & 15;   // o-thread: 4 cols
    const int ty  = tid >> 4;   // i-thread: 4 rows

    const int lr0 = tid >> 2;               // load rows 0..63
    const int lq0 = (tid & 3) * 2;          // k-quads {0,2,4,6}
    const int lq1 = lq0 + 1;

    float4 vx[2][2], vw[2][2];
    {
        const float* px = &x[(i0 + lr0) * NIN + kbase];
        const float* pw = &W[(o0 + lr0) * (2 * NIN) + woff + kbase];
        vx[0][0] = *reinterpret_cast<const float4*>(px + lq0 * 4);
        vx[0][1] = *reinterpret_cast<const float4*>(px + lq1 * 4);
        vw[0][0] = *reinterpret_cast<const float4*>(pw + lq0 * 4);
        vw[0][1] = *reinterpret_cast<const float4*>(pw + lq1 * 4);
    }

    float acc[4][4];
    #pragma unroll
    for (int r = 0; r < 4; r++)
        #pragma unroll
        for (int q = 0; q < 4; q++) acc[r][q] = 0.f;

    #pragma unroll
    for (int ch = 0; ch < 4; ch++) {
        const int cur = ch & 1;
        {
            float4 v = vx[cur][0];
            xs[(lq0 * 4 + 0) * 68 + lr0] = v.x;
            xs[(lq0 * 4 + 1) * 68 + lr0] = v.y;
            xs[(lq0 * 4 + 2) * 68 + lr0] = v.z;
            xs[(lq0 * 4 + 3) * 68 + lr0] = v.w;
            v = vx[cur][1];
            xs[(lq1 * 4 + 0) * 68 + lr0] = v.x;
            xs[(lq1 * 4 + 1) * 68 + lr0] = v.y;
            xs[(lq1 * 4 + 2) * 68 + lr0] = v.z;
            xs[(lq1 * 4 + 3) * 68 + lr0] = v.w;
            v = vw[cur][0];
            ws[(lq0 * 4 + 0) * 68 + lr0] = v.x;
            ws[(lq0 * 4 + 1) * 68 + lr0] = v.y;
            ws[(lq0 * 4 + 2) * 68 + lr0] = v.z;
            ws[(lq0 * 4 + 3) * 68 + lr0] = v.w;
            v = vw[cur][1];
            ws[(lq1 * 4 + 0) * 68 + lr0] = v.x;
            ws[(lq1 * 4 + 1) * 68 + lr0] = v.y;
            ws[(lq1 * 4 + 2) * 68 + lr0] = v.z;
            ws[(lq1 * 4 + 3) * 68 + lr0] = v.w;
        }
        __syncthreads();

        if (ch < 3) {
            const int nxt = cur ^ 1;
            const int k0  = kbase + (ch + 1) * 32;
            const float* px = &x[(i0 + lr0) * NIN + k0];
            const float* pw = &W[(o0 + lr0) * (2 * NIN) + woff + k0];
            vx[nxt][0] = *reinterpret_cast<const float4*>(px + lq0 * 4);
            vx[nxt][1] = *reinterpret_cast<const float4*>(px + lq1 * 4);
            vw[nxt][0] = *reinterpret_cast<const float4*>(pw + lq0 * 4);
            vw[nxt][1] = *reinterpret_cast<const float4*>(pw + lq1 * 4);
        }

        #pragma unroll
        for (int kk = 0; kk < 32; kk++) {
            float4 aq = *reinterpret_cast<const float4*>(&xs[kk * 68 + ty * 4]);
            float4 wq = *reinterpret_cast<const float4*>(&ws[kk * 68 + tx * 4]);
            acc[0][0] += aq.x * wq.x; acc[0][1] += aq.x * wq.y;
            acc[0][2] += aq.x * wq.z; acc[0][3] += aq.x * wq.w;
            acc[1][0] += aq.y * wq.x; acc[1][1] += aq.y * wq.y;
            acc[1][2] += aq.y * wq.z; acc[1][3] += aq.y * wq.w;
            acc[2][0] += aq.z * wq.x; acc[2][1] += aq.z * wq.y;
            acc[2][2] += aq.z * wq.z; acc[2][3] += aq.z * wq.w;
            acc[3][0] += aq.w * wq.x; acc[3][1] += aq.w * wq.y;
            acc[3][2] += aq.w * wq.z; acc[3][3] += aq.w * wq.w;
        }
        __syncthreads();
    }

    float4 bias = make_float4(0.f, 0.f, 0.f, 0.f);
    if (half == 0 && ks == 0)
        bias = *reinterpret_cast<const float4*>(&b[o0 + tx * 4]);

    float* dst = (half == 0) ? (ks == 0 ? g_A0 : g_A1)
                             : (ks == 0 ? g_B0 : g_B1);
    #pragma unroll
    for (int r = 0; r < 4; r++) {
        int i = i0 + ty * 4 + r;
        float4 outv = make_float4(acc[r][0] + bias.x,
                                  acc[r][1] + bias.y,
                                  acc[r][2] + bias.z,
                                  acc[r][3] + bias.w);
        *reinterpret_cast<float4*>(&dst[i * NOUT + o0 + tx * 4]) = outv;
    }

    // Fire PDL: kernel 2 may start launching now (sees g_* when all CTAs fire)
    asm volatile("griddepcontrol.launch_dependents;" ::: "memory");

    // Producer barrier among the 128 co-resident GEMM blocks.
    __threadfence();
    __syncthreads();
    if (tid == 0) {
        red_release_add(&g_cnt, 1);
        while (ld_acquire(&g_cnt) < 128) __nanosleep(64);
        // last block past the spin resets counters for the next graph replay
        int old = atomicAdd(&g_pass, 1);
        if (old == 127) {
            atomicExch(&g_cnt, 0);
            atomicExch(&g_pass, 0);
        }
    }
    __syncthreads();

    // Each GEMM block writes 2 of the first 256 output tiles.
    write_tile(bid * 2 + 0, out, sB, tid);
    write_tile(bid * 2 + 1, out, sB, tid);
}

// ---------------------------------------------------------------------------
// Kernel 2: writer for the remaining 768 tiles (PDL-dependent).
// ---------------------------------------------------------------------------
__global__ void __launch_bounds__(256)
sym_writer_kernel(float* __restrict__ out)
{
    __shared__ __align__(16) float sB[TS * NOUT];
    asm volatile("griddepcontrol.wait;" ::: "memory");
    write_tile(256 + blockIdx.x, out, sB, threadIdx.x);
}

extern "C" void kernel_launch(void* const* d_in, const int* in_sizes, int n_in,
                              void* d_out, int out_size)
{
    const float* x = (const float*)d_in[0];   // [512, 256]
    const float* W = (const float*)d_in[1];   // [256, 512]
    const float* b = (const float*)d_in[2];   // [256]
    float* out = (float*)d_out;               // [512, 512, 256]

    // Kernel 1: GEMM + barrier + first 256 output tiles (128 blocks)
    gemm_writer_kernel<<<128, 256>>>(x, W, b, out);

    // Kernel 2: remaining 768 tiles, PDL-overlapped with kernel 1's tail.
    cudaLaunchConfig_t cfg = {};
    cfg.gridDim  = dim3(768, 1, 1);
    cfg.blockDim = dim3(256, 1, 1);
    cfg.dynamicSmemBytes = 0;
    cfg.stream = 0;
    cudaLaunchAttribute attrs[1];
    attrs[0].id = cudaLaunchAttributeProgrammaticStreamSerialization;
    attrs[0].val.programmaticStreamSerializationAllowed = 1;
    cfg.attrs = attrs;
    cfg.numAttrs = 1;
    cudaLaunchKernelEx(&cfg, sym_writer_kernel, out);
}